// round 2
// baseline (speedup 1.0000x reference)
#include <cuda_runtime.h>
#include <cuda_bf16.h>

#define NN 100000
#define EE 1600000
#define DD 128
#define CC 47
#define EPS 1e-5f

// -------- scratch (device globals; no runtime allocation) --------
__device__ float g_x[NN * DD];     // current node features (residual stream)
__device__ float g_msg[NN * DD];   // neighbor sum
__device__ float g_h[NN * DD];     // pre-BN layer output
__device__ float g_cnt[NN];        // in-degree
__device__ float g_colsum[DD];
__device__ float g_colsumsq[DD];
__device__ float g_scale[DD];
__device__ float g_shift[DD];

// -------- utility kernels --------
__global__ void copy_x_kernel(const float* __restrict__ x) {
    int tid = blockIdx.x * blockDim.x + threadIdx.x;
    int stride = gridDim.x * blockDim.x;
    const float4* src = (const float4*)x;
    float4* dst = (float4*)g_x;
    for (int i = tid; i < NN * DD / 4; i += stride) dst[i] = src[i];
}

__global__ void zero_kernel() {
    int tid = blockIdx.x * blockDim.x + threadIdx.x;
    int stride = gridDim.x * blockDim.x;
    float4 z = make_float4(0.f, 0.f, 0.f, 0.f);
    float4* msg4 = (float4*)g_msg;
    for (int i = tid; i < NN * DD / 4; i += stride) msg4[i] = z;
    for (int i = tid; i < NN; i += stride) g_cnt[i] = 0.f;
    if (tid < DD) { g_colsum[tid] = 0.f; g_colsumsq[tid] = 0.f; }
}

// -------- edge scatter: msg[dst] += x[src]; cnt[dst] += 1 --------
__global__ void scatter_kernel(const int* __restrict__ ei) {
    int idx = blockIdx.x * blockDim.x + threadIdx.x;   // < E*32 = 51.2M
    if (idx >= EE * 32) return;
    int e = idx >> 5;
    int c = (idx & 31) * 4;
    int src = ei[e];
    int dst = ei[EE + e];
    float4 v = *(const float4*)&g_x[src * DD + c];
    float4* p = (float4*)&g_msg[dst * DD + c];
#if __CUDA_ARCH__ >= 900
    atomicAdd(p, v);
#else
    atomicAdd(&((float*)p)[0], v.x);
    atomicAdd(&((float*)p)[1], v.y);
    atomicAdd(&((float*)p)[2], v.z);
    atomicAdd(&((float*)p)[3], v.w);
#endif
    if ((idx & 31) == 0) atomicAdd(&g_cnt[dst], 1.0f);
}

// -------- layer GEMM: h = x @ Wl^T + bl + (msg/cnt) @ Wr^T --------
// Treated as a single K=256 GEMM: a = [x | mean], W = [Wl | Wr].
// Tile: 64 rows x 128 cols per block, 256 threads, 4x8 per thread.
#define TM 64
#define KC 16
__global__ void __launch_bounds__(256) gemm_layer_kernel(
    const float* __restrict__ Wl, const float* __restrict__ bl,
    const float* __restrict__ Wr)
{
    __shared__ __align__(16) float as[TM * 20];      // [m][k], row stride 20
    __shared__ __align__(16) float ws[KC * 132];     // [k][j], row stride 132
    __shared__ float rcnt_s[TM];

    int tid = threadIdx.x;
    int row0 = blockIdx.x * TM;

    if (tid < TM) {
        int r = row0 + tid;
        float c = (r < NN) ? g_cnt[r] : 1.0f;
        rcnt_s[tid] = 1.0f / fmaxf(c, 1.0f);
    }
    __syncthreads();

    int cg = tid & 15;            // 16 col-groups
    int rg = tid >> 4;            // 16 row-groups
    int j0 = cg * 8;
    int m0 = rg * 4;

    float acc[4][8];
#pragma unroll
    for (int i = 0; i < 4; i++)
#pragma unroll
        for (int c = 0; c < 8; c++) acc[i][c] = 0.f;

    int lm = tid >> 2;            // a-tile row (0..63)
    int lq = tid & 3;             // a-tile k-quad

    for (int kc = 0; kc < 2 * DD; kc += KC) {
        // --- load A tile (64 x 16): k<128 -> x, k>=128 -> msg * rcnt ---
        {
            int row = row0 + lm;
            int kg = kc + lq * 4;
            float4 v = make_float4(0.f, 0.f, 0.f, 0.f);
            if (row < NN) {
                if (kg < DD) {
                    v = *(const float4*)&g_x[row * DD + kg];
                } else {
                    v = *(const float4*)&g_msg[row * DD + (kg - DD)];
                    float rc = rcnt_s[lm];
                    v.x *= rc; v.y *= rc; v.z *= rc; v.w *= rc;
                }
            }
            *(float4*)&as[lm * 20 + lq * 4] = v;
        }
        // --- load W tile (transposed into [k][j]) ---
#pragma unroll
        for (int l = 0; l < 2; l++) {
            int idx = tid + l * 256;
            int j = idx >> 2;
            int q = idx & 3;
            int kg = kc + q * 4;
            const float* Wsrc = (kg < DD) ? Wl : Wr;
            float4 v = *(const float4*)&Wsrc[j * DD + (kg & (DD - 1))];
            ws[(q * 4 + 0) * 132 + j] = v.x;
            ws[(q * 4 + 1) * 132 + j] = v.y;
            ws[(q * 4 + 2) * 132 + j] = v.z;
            ws[(q * 4 + 3) * 132 + j] = v.w;
        }
        __syncthreads();

#pragma unroll
        for (int kk = 0; kk < KC; kk++) {
            float a0 = as[(m0 + 0) * 20 + kk];
            float a1 = as[(m0 + 1) * 20 + kk];
            float a2 = as[(m0 + 2) * 20 + kk];
            float a3 = as[(m0 + 3) * 20 + kk];
            float4 w0 = *(float4*)&ws[kk * 132 + j0];
            float4 w1 = *(float4*)&ws[kk * 132 + j0 + 4];
            acc[0][0] += a0 * w0.x; acc[0][1] += a0 * w0.y; acc[0][2] += a0 * w0.z; acc[0][3] += a0 * w0.w;
            acc[0][4] += a0 * w1.x; acc[0][5] += a0 * w1.y; acc[0][6] += a0 * w1.z; acc[0][7] += a0 * w1.w;
            acc[1][0] += a1 * w0.x; acc[1][1] += a1 * w0.y; acc[1][2] += a1 * w0.z; acc[1][3] += a1 * w0.w;
            acc[1][4] += a1 * w1.x; acc[1][5] += a1 * w1.y; acc[1][6] += a1 * w1.z; acc[1][7] += a1 * w1.w;
            acc[2][0] += a2 * w0.x; acc[2][1] += a2 * w0.y; acc[2][2] += a2 * w0.z; acc[2][3] += a2 * w0.w;
            acc[2][4] += a2 * w1.x; acc[2][5] += a2 * w1.y; acc[2][6] += a2 * w1.z; acc[2][7] += a2 * w1.w;
            acc[3][0] += a3 * w0.x; acc[3][1] += a3 * w0.y; acc[3][2] += a3 * w0.z; acc[3][3] += a3 * w0.w;
            acc[3][4] += a3 * w1.x; acc[3][5] += a3 * w1.y; acc[3][6] += a3 * w1.z; acc[3][7] += a3 * w1.w;
        }
        __syncthreads();
    }

    // epilogue: add bias, write h
#pragma unroll
    for (int i = 0; i < 4; i++) {
        int row = row0 + m0 + i;
        if (row < NN) {
#pragma unroll
            for (int c = 0; c < 8; c++)
                g_h[row * DD + j0 + c] = acc[i][c] + __ldg(&bl[j0 + c]);
        }
    }
}

// -------- BN stats: per-column sum and sumsq over all rows --------
__global__ void stats_kernel() {
    int j = threadIdx.x;   // 128 threads = 1 col each
    float s = 0.f, sq = 0.f;
    for (int r = blockIdx.x; r < NN; r += gridDim.x) {
        float v = g_h[r * DD + j];
        s += v;
        sq += v * v;
    }
    atomicAdd(&g_colsum[j], s);
    atomicAdd(&g_colsumsq[j], sq);
}

__global__ void bn_final_kernel(const float* __restrict__ g, const float* __restrict__ b) {
    int j = threadIdx.x;
    float mu = g_colsum[j] * (1.0f / NN);
    float var = g_colsumsq[j] * (1.0f / NN) - mu * mu;
    float sc = g[j] * rsqrtf(var + EPS);
    g_scale[j] = sc;
    g_shift[j] = b[j] - mu * sc;
}

// -------- residual: x += relu(h * scale + shift) --------
__global__ void residual_kernel() {
    int i = blockIdx.x * blockDim.x + threadIdx.x;  // over N*D/4
    if (i >= NN * DD / 4) return;
    int j = (i & 31) * 4;
    float4 h = ((float4*)g_h)[i];
    float4 x = ((float4*)g_x)[i];
    float4 sc = *(float4*)&g_scale[j];
    float4 sh = *(float4*)&g_shift[j];
    x.x += fmaxf(h.x * sc.x + sh.x, 0.f);
    x.y += fmaxf(h.y * sc.y + sh.y, 0.f);
    x.z += fmaxf(h.z * sc.z + sh.z, 0.f);
    x.w += fmaxf(h.w * sc.w + sh.w, 0.f);
    ((float4*)g_x)[i] = x;
}

// -------- final classifier: out = x @ lin_W^T + lin_b  [N, 47] --------
__global__ void final_gemm_kernel(const float* __restrict__ W,
                                  const float* __restrict__ b,
                                  float* __restrict__ out)
{
    __shared__ __align__(16) float xs[8][DD];
    int rb = blockIdx.x * 8;
    int tid = threadIdx.y * 48 + threadIdx.x;  // blockDim (48, 8) = 384
    if (tid < 256) {
        int m = tid >> 5;
        int q = tid & 31;
        int row = rb + m;
        float4 v = make_float4(0.f, 0.f, 0.f, 0.f);
        if (row < NN) v = *(const float4*)&g_x[row * DD + q * 4];
        *(float4*)&xs[m][q * 4] = v;
    }
    __syncthreads();

    int c = threadIdx.x;     // 0..47; only 0..46 are valid classes
    int row = rb + threadIdx.y;
    if (row >= NN || c >= CC) return;   // <-- FIX: c==47 was writing OOB/aliasing next row
    float acc = 0.f;
#pragma unroll
    for (int k = 0; k < DD; k += 4) {
        float4 xv = *(float4*)&xs[threadIdx.y][k];
        float4 wv = *(const float4*)&W[c * DD + k];
        acc += xv.x * wv.x + xv.y * wv.y + xv.z * wv.z + xv.w * wv.w;
    }
    out[row * CC + c] = acc + __ldg(&b[c]);
}

// -------- driver --------
extern "C" void kernel_launch(void* const* d_in, const int* in_sizes, int n_in,
                              void* d_out, int out_size) {
    const float* x  = (const float*)d_in[0];
    const int*   ei = (const int*)d_in[1];
    float* out = (float*)d_out;

    copy_x_kernel<<<2048, 256>>>(x);

    for (int layer = 0; layer < 3; layer++) {
        const float* Wl = (const float*)d_in[2 + layer * 5 + 0];
        const float* bl = (const float*)d_in[2 + layer * 5 + 1];
        const float* Wr = (const float*)d_in[2 + layer * 5 + 2];
        const float* bg = (const float*)d_in[2 + layer * 5 + 3];
        const float* bb = (const float*)d_in[2 + layer * 5 + 4];

        zero_kernel<<<2048, 256>>>();
        scatter_kernel<<<(EE * 32 + 255) / 256, 256>>>(ei);
        gemm_layer_kernel<<<(NN + TM - 1) / TM, 256>>>(Wl, bl, Wr);
        stats_kernel<<<1024, 128>>>();
        bn_final_kernel<<<1, 128>>>(bg, bb);
        residual_kernel<<<(NN * DD / 4 + 255) / 256, 256>>>();
    }

    const float* linW = (const float*)d_in[17];
    const float* linb = (const float*)d_in[18];
    final_gemm_kernel<<<(NN + 7) / 8, dim3(48, 8)>>>(linW, linb, out);
}

// round 3
// speedup vs baseline: 1.4146x; 1.4146x over previous
#include <cuda_runtime.h>
#include <cuda_bf16.h>

#define NN 100000
#define EE 1600000
#define DD 128
#define CC 47
#define EPS 1e-5f

// -------- scratch (device globals; no runtime allocation) --------
__device__ float g_x[NN * DD];     // current node features (residual stream)
__device__ float g_msg[NN * DD];   // neighbor MEAN (division folded into gather)
__device__ float g_h[NN * DD];     // pre-BN layer output
__device__ int   g_deg[NN];        // in-degree
__device__ int   g_rowptr[NN];     // CSR row start
__device__ int   g_cursor[NN];     // fill cursors
__device__ int   g_srcs[EE];       // CSR column (src) indices
__device__ float g_colsum[DD];
__device__ float g_colsumsq[DD];
__device__ float g_scale[DD];
__device__ float g_shift[DD];

// -------- copy input x into residual stream; zero degree --------
__global__ void copy_x_kernel(const float* __restrict__ x) {
    int tid = blockIdx.x * blockDim.x + threadIdx.x;
    int stride = gridDim.x * blockDim.x;
    const float4* src = (const float4*)x;
    float4* dst = (float4*)g_x;
    for (int i = tid; i < NN * DD / 4; i += stride) dst[i] = src[i];
    for (int i = tid; i < NN; i += stride) g_deg[i] = 0;
}

// -------- CSR build --------
__global__ void hist_kernel(const int* __restrict__ ei) {
    int e = blockIdx.x * blockDim.x + threadIdx.x;
    if (e >= EE) return;
    atomicAdd(&g_deg[ei[EE + e]], 1);
}

// single-block exclusive scan over g_deg -> g_rowptr, g_cursor
__global__ void scan_kernel() {
    __shared__ int wsums[32];
    int tid = threadIdx.x;            // 1024 threads
    int lane = tid & 31, wid = tid >> 5;
    int carry = 0;
    for (int base = 0; base < NN; base += 1024) {
        int i = base + tid;
        int v = (i < NN) ? g_deg[i] : 0;
        int x = v;
#pragma unroll
        for (int d = 1; d < 32; d <<= 1) {
            int y = __shfl_up_sync(0xffffffffu, x, d);
            if (lane >= d) x += y;
        }
        if (lane == 31) wsums[wid] = x;
        __syncthreads();
        if (wid == 0) {
            int s = wsums[lane];
#pragma unroll
            for (int d = 1; d < 32; d <<= 1) {
                int y = __shfl_up_sync(0xffffffffu, s, d);
                if (lane >= d) s += y;
            }
            wsums[lane] = s;
        }
        __syncthreads();
        int warpoff = (wid > 0) ? wsums[wid - 1] : 0;
        int excl = carry + warpoff + x - v;
        if (i < NN) { g_rowptr[i] = excl; g_cursor[i] = excl; }
        carry += wsums[31];
        __syncthreads();
    }
}

__global__ void fill_kernel(const int* __restrict__ ei) {
    int e = blockIdx.x * blockDim.x + threadIdx.x;
    if (e >= EE) return;
    int dst = ei[EE + e];
    int pos = atomicAdd(&g_cursor[dst], 1);
    g_srcs[pos] = ei[e];
}

// -------- aggregation: warp per node, mean of x[src] --------
__global__ void gather_kernel() {
    int warp = (blockIdx.x * blockDim.x + threadIdx.x) >> 5;
    int lane = threadIdx.x & 31;
    if (warp >= NN) return;
    int start = g_rowptr[warp];
    int deg = g_deg[warp];
    float4 acc = make_float4(0.f, 0.f, 0.f, 0.f);
    for (int e = 0; e < deg; e++) {
        int src = g_srcs[start + e];
        float4 v = *(const float4*)&g_x[src * DD + lane * 4];
        acc.x += v.x; acc.y += v.y; acc.z += v.z; acc.w += v.w;
    }
    float rc = 1.0f / (float)(deg > 0 ? deg : 1);
    acc.x *= rc; acc.y *= rc; acc.z *= rc; acc.w *= rc;
    *(float4*)&g_msg[warp * DD + lane * 4] = acc;
}

// -------- layer GEMM: h = [x | mean] @ [Wl | Wr]^T + bl --------
// Tile 128x128, K-chunk 16, 256 threads, 8x8 per thread.
#define GM 128
#define GK 16
__global__ void __launch_bounds__(256) gemm_layer_kernel(
    const float* __restrict__ Wl, const float* __restrict__ bl,
    const float* __restrict__ Wr)
{
    __shared__ __align__(16) float as[GK][132];   // [k][m]
    __shared__ __align__(16) float ws[GK][132];   // [k][j]

    int tid = threadIdx.x;
    int row0 = blockIdx.x * GM;
    int mt = tid >> 4;            // 0..15
    int jt = tid & 15;            // 0..15
    int m0 = mt * 8, j0 = jt * 8;

    float acc[8][8];
#pragma unroll
    for (int i = 0; i < 8; i++)
#pragma unroll
        for (int j = 0; j < 8; j++) acc[i][j] = 0.f;

    int lrow = tid >> 2;          // 0..63
    int lkq = tid & 3;            // k-quad 0..3

    for (int kc = 0; kc < 2 * DD; kc += GK) {
        // --- A tile: 128 rows x 16 k (k<128 -> x, else mean) ---
#pragma unroll
        for (int l = 0; l < 2; l++) {
            int row = row0 + lrow + l * 64;
            int kg = kc + lkq * 4;
            float4 v = make_float4(0.f, 0.f, 0.f, 0.f);
            if (row < NN) {
                const float* p = (kg < DD) ? &g_x[row * DD + kg]
                                           : &g_msg[row * DD + (kg - DD)];
                v = *(const float4*)p;
            }
            int m = lrow + l * 64;
            as[lkq * 4 + 0][m] = v.x;
            as[lkq * 4 + 1][m] = v.y;
            as[lkq * 4 + 2][m] = v.z;
            as[lkq * 4 + 3][m] = v.w;
        }
        // --- W tile: 128 j x 16 k ---
#pragma unroll
        for (int l = 0; l < 2; l++) {
            int j = (tid >> 2) + l * 64;
            int kg = kc + (tid & 3) * 4;
            const float* Wsrc = (kg < DD) ? Wl : Wr;
            float4 v = *(const float4*)&Wsrc[j * DD + (kg & (DD - 1))];
            int kb = (tid & 3) * 4;
            ws[kb + 0][j] = v.x;
            ws[kb + 1][j] = v.y;
            ws[kb + 2][j] = v.z;
            ws[kb + 3][j] = v.w;
        }
        __syncthreads();

#pragma unroll
        for (int kk = 0; kk < GK; kk++) {
            float a[8], w[8];
            *(float4*)&a[0] = *(float4*)&as[kk][m0];
            *(float4*)&a[4] = *(float4*)&as[kk][m0 + 4];
            *(float4*)&w[0] = *(float4*)&ws[kk][j0];
            *(float4*)&w[4] = *(float4*)&ws[kk][j0 + 4];
#pragma unroll
            for (int i = 0; i < 8; i++)
#pragma unroll
                for (int j = 0; j < 8; j++) acc[i][j] += a[i] * w[j];
        }
        __syncthreads();
    }

    float4 b0 = *(const float4*)&bl[j0];
    float4 b1 = *(const float4*)&bl[j0 + 4];
#pragma unroll
    for (int i = 0; i < 8; i++) {
        int row = row0 + m0 + i;
        if (row < NN) {
            float4 o0 = make_float4(acc[i][0] + b0.x, acc[i][1] + b0.y,
                                    acc[i][2] + b0.z, acc[i][3] + b0.w);
            float4 o1 = make_float4(acc[i][4] + b1.x, acc[i][5] + b1.y,
                                    acc[i][6] + b1.z, acc[i][7] + b1.w);
            *(float4*)&g_h[row * DD + j0] = o0;
            *(float4*)&g_h[row * DD + j0 + 4] = o1;
        }
    }
}

// -------- BN --------
__global__ void zero_stats_kernel() {
    int j = threadIdx.x;
    g_colsum[j] = 0.f;
    g_colsumsq[j] = 0.f;
}

__global__ void stats_kernel() {
    int j = threadIdx.x;   // 128 threads = 1 col each
    float s = 0.f, sq = 0.f;
    for (int r = blockIdx.x; r < NN; r += gridDim.x) {
        float v = g_h[r * DD + j];
        s += v;
        sq += v * v;
    }
    atomicAdd(&g_colsum[j], s);
    atomicAdd(&g_colsumsq[j], sq);
}

__global__ void bn_final_kernel(const float* __restrict__ g, const float* __restrict__ b) {
    int j = threadIdx.x;
    float mu = g_colsum[j] * (1.0f / NN);
    float var = g_colsumsq[j] * (1.0f / NN) - mu * mu;
    float sc = g[j] * rsqrtf(var + EPS);
    g_scale[j] = sc;
    g_shift[j] = b[j] - mu * sc;
}

// -------- residual: x += relu(h * scale + shift) --------
__global__ void residual_kernel() {
    int i = blockIdx.x * blockDim.x + threadIdx.x;  // over N*D/4
    if (i >= NN * DD / 4) return;
    int j = (i & 31) * 4;
    float4 h = ((float4*)g_h)[i];
    float4 x = ((float4*)g_x)[i];
    float4 sc = *(float4*)&g_scale[j];
    float4 sh = *(float4*)&g_shift[j];
    x.x += fmaxf(h.x * sc.x + sh.x, 0.f);
    x.y += fmaxf(h.y * sc.y + sh.y, 0.f);
    x.z += fmaxf(h.z * sc.z + sh.z, 0.f);
    x.w += fmaxf(h.w * sc.w + sh.w, 0.f);
    ((float4*)g_x)[i] = x;
}

// -------- final classifier: out = x @ lin_W^T + lin_b  [N, 47] --------
__global__ void final_gemm_kernel(const float* __restrict__ W,
                                  const float* __restrict__ b,
                                  float* __restrict__ out)
{
    __shared__ __align__(16) float xs[8][DD];
    int rb = blockIdx.x * 8;
    int tid = threadIdx.y * 48 + threadIdx.x;  // blockDim (48, 8) = 384
    if (tid < 256) {
        int m = tid >> 5;
        int q = tid & 31;
        int row = rb + m;
        float4 v = make_float4(0.f, 0.f, 0.f, 0.f);
        if (row < NN) v = *(const float4*)&g_x[row * DD + q * 4];
        *(float4*)&xs[m][q * 4] = v;
    }
    __syncthreads();

    int c = threadIdx.x;     // 0..47; only 0..46 valid
    int row = rb + threadIdx.y;
    if (row >= NN || c >= CC) return;
    float acc = 0.f;
#pragma unroll
    for (int k = 0; k < DD; k += 4) {
        float4 xv = *(float4*)&xs[threadIdx.y][k];
        float4 wv = *(const float4*)&W[c * DD + k];
        acc += xv.x * wv.x + xv.y * wv.y + xv.z * wv.z + xv.w * wv.w;
    }
    out[row * CC + c] = acc + __ldg(&b[c]);
}

// -------- driver --------
extern "C" void kernel_launch(void* const* d_in, const int* in_sizes, int n_in,
                              void* d_out, int out_size) {
    const float* x  = (const float*)d_in[0];
    const int*   ei = (const int*)d_in[1];
    float* out = (float*)d_out;

    copy_x_kernel<<<2048, 256>>>(x);
    hist_kernel<<<(EE + 255) / 256, 256>>>(ei);
    scan_kernel<<<1, 1024>>>();
    fill_kernel<<<(EE + 255) / 256, 256>>>(ei);

    for (int layer = 0; layer < 3; layer++) {
        const float* Wl = (const float*)d_in[2 + layer * 5 + 0];
        const float* bl = (const float*)d_in[2 + layer * 5 + 1];
        const float* Wr = (const float*)d_in[2 + layer * 5 + 2];
        const float* bg = (const float*)d_in[2 + layer * 5 + 3];
        const float* bb = (const float*)d_in[2 + layer * 5 + 4];

        gather_kernel<<<(NN * 32 + 255) / 256, 256>>>();
        gemm_layer_kernel<<<(NN + GM - 1) / GM, 256>>>(Wl, bl, Wr);
        zero_stats_kernel<<<1, 128>>>();
        stats_kernel<<<1024, 128>>>();
        bn_final_kernel<<<1, 128>>>(bg, bb);
        residual_kernel<<<(NN * DD / 4 + 255) / 256, 256>>>();
    }

    const float* linW = (const float*)d_in[17];
    const float* linb = (const float*)d_in[18];
    final_gemm_kernel<<<(NN + 7) / 8, dim3(48, 8)>>>(linW, linb, out);
}

// round 5
// speedup vs baseline: 1.4366x; 1.0155x over previous
#include <cuda_runtime.h>
#include <cuda_bf16.h>
#include <cstdint>

#define NN 100000
#define EE 1600000
#define DD 128
#define CC 47
#define EPS 1e-5f

// -------- scratch (device globals; no runtime allocation) --------
__device__ float g_x[NN * DD];
__device__ float g_msg[NN * DD];
__device__ float g_h[NN * DD];
__device__ int   g_deg[NN];
__device__ int   g_rowptr[NN];
__device__ int   g_cursor[NN];
__device__ int   g_srcs[EE];
__device__ float g_colsum[DD];
__device__ float g_colsumsq[DD];
__device__ float g_scale[DD];
__device__ float g_shift[DD];

// ==================== helpers ====================
__device__ __forceinline__ uint32_t f2tf32(float f) {
    uint32_t r;
    asm("cvt.rna.tf32.f32 %0, %1;" : "=r"(r) : "f"(f));
    return r;
}
__device__ __forceinline__ void tf32_split(float f, uint32_t& hi, uint32_t& lo) {
    uint32_t h = f2tf32(f);
    float r = f - __uint_as_float(h);
    lo = f2tf32(r);
    hi = h;
}
__device__ __forceinline__ void mma_tf32(float* d, const uint32_t* a, const uint32_t* b) {
    asm volatile(
        "mma.sync.aligned.m16n8k8.row.col.f32.tf32.tf32.f32 "
        "{%0,%1,%2,%3}, {%4,%5,%6,%7}, {%8,%9}, {%0,%1,%2,%3};"
        : "+f"(d[0]), "+f"(d[1]), "+f"(d[2]), "+f"(d[3])
        : "r"(a[0]), "r"(a[1]), "r"(a[2]), "r"(a[3]), "r"(b[0]), "r"(b[1]));
}

// ==================== housekeeping ====================
__global__ void copy_x_kernel(const float* __restrict__ x) {
    int tid = blockIdx.x * blockDim.x + threadIdx.x;
    int stride = gridDim.x * blockDim.x;
    const float4* src = (const float4*)x;
    float4* dst = (float4*)g_x;
    for (int i = tid; i < NN * DD / 4; i += stride) dst[i] = src[i];
    for (int i = tid; i < NN; i += stride) g_deg[i] = 0;
}

__global__ void hist_kernel(const int* __restrict__ ei) {
    int e = blockIdx.x * blockDim.x + threadIdx.x;
    if (e >= EE) return;
    atomicAdd(&g_deg[ei[EE + e]], 1);
}

__global__ void scan_kernel() {
    __shared__ int wsums[32];
    int tid = threadIdx.x;            // 1024 threads
    int lane = tid & 31, wid = tid >> 5;
    int carry = 0;
    for (int base = 0; base < NN; base += 1024) {
        int i = base + tid;
        int v = (i < NN) ? g_deg[i] : 0;
        int x = v;
#pragma unroll
        for (int d = 1; d < 32; d <<= 1) {
            int y = __shfl_up_sync(0xffffffffu, x, d);
            if (lane >= d) x += y;
        }
        if (lane == 31) wsums[wid] = x;
        __syncthreads();
        if (wid == 0) {
            int s = wsums[lane];
#pragma unroll
            for (int d = 1; d < 32; d <<= 1) {
                int y = __shfl_up_sync(0xffffffffu, s, d);
                if (lane >= d) s += y;
            }
            wsums[lane] = s;
        }
        __syncthreads();
        int warpoff = (wid > 0) ? wsums[wid - 1] : 0;
        int excl = carry + warpoff + x - v;
        if (i < NN) { g_rowptr[i] = excl; g_cursor[i] = excl; }
        carry += wsums[31];
        __syncthreads();
    }
}

__global__ void fill_kernel(const int* __restrict__ ei) {
    int e = blockIdx.x * blockDim.x + threadIdx.x;
    if (e >= EE) return;
    int dst = ei[EE + e];
    int pos = atomicAdd(&g_cursor[dst], 1);
    g_srcs[pos] = ei[e];
}

// -------- aggregation: warp per node, mean of x[src] --------
__global__ void gather_kernel() {
    int warp = (blockIdx.x * blockDim.x + threadIdx.x) >> 5;
    int lane = threadIdx.x & 31;
    if (warp >= NN) return;
    int start = g_rowptr[warp];
    int deg = g_deg[warp];
    float4 acc0 = make_float4(0.f, 0.f, 0.f, 0.f);
    float4 acc1 = make_float4(0.f, 0.f, 0.f, 0.f);
    int e = 0;
#pragma unroll 2
    for (; e + 2 <= deg; e += 2) {
        int s0 = __ldg(&g_srcs[start + e]);
        int s1 = __ldg(&g_srcs[start + e + 1]);
        float4 v0 = *(const float4*)&g_x[s0 * DD + lane * 4];
        float4 v1 = *(const float4*)&g_x[s1 * DD + lane * 4];
        acc0.x += v0.x; acc0.y += v0.y; acc0.z += v0.z; acc0.w += v0.w;
        acc1.x += v1.x; acc1.y += v1.y; acc1.z += v1.z; acc1.w += v1.w;
    }
    if (e < deg) {
        int s0 = __ldg(&g_srcs[start + e]);
        float4 v0 = *(const float4*)&g_x[s0 * DD + lane * 4];
        acc0.x += v0.x; acc0.y += v0.y; acc0.z += v0.z; acc0.w += v0.w;
    }
    float rc = 1.0f / (float)(deg > 0 ? deg : 1);
    acc0.x = (acc0.x + acc1.x) * rc;
    acc0.y = (acc0.y + acc1.y) * rc;
    acc0.z = (acc0.z + acc1.z) * rc;
    acc0.w = (acc0.w + acc1.w) * rc;
    *(float4*)&g_msg[warp * DD + lane * 4] = acc0;
}

// ==================== mma.sync tf32 layer GEMM ====================
// h[m][j] = sum_k x[m][k]*Wl[j][k] + sum_k mean[m][k]*Wr[j][k]  (bias dropped: BN-invariant)
// fp32 emulated via tf32 hi/lo split: d += ah*bh + ah*bl + al*bh.
// CTA tile 128x128, 8 warps (4 M x 2 N), warp tile 32x64, K chunked by 16.
#define PAD 20
__global__ void __launch_bounds__(256, 2) gemm_mma_kernel(
    const float* __restrict__ Wl, const float* __restrict__ Wr)
{
    __shared__ uint32_t as_hi[128 * PAD];
    __shared__ uint32_t as_lo[128 * PAD];
    __shared__ uint32_t bs_hi[128 * PAD];
    __shared__ uint32_t bs_lo[128 * PAD];

    int tid = threadIdx.x;
    int wid = tid >> 5, lane = tid & 31;
    int grp = lane >> 2, thr = lane & 3;
    int row0 = blockIdx.x * 128;
    int mbase = (wid & 3) * 32;
    int nbase = (wid >> 2) * 64;

    float d[2][8][4];
#pragma unroll
    for (int mt = 0; mt < 2; mt++)
#pragma unroll
        for (int nt = 0; nt < 8; nt++)
#pragma unroll
            for (int i = 0; i < 4; i++) d[mt][nt][i] = 0.f;

    int lr = tid >> 1;           // 0..127 (row)
    int lc = (tid & 1) * 8;      // 0 or 8 (k offset within chunk)

    for (int kc = 0; kc < 2 * DD; kc += 16) {
        const float* Asrc = (kc < DD) ? g_x : g_msg;
        const float* Bsrc = (kc < DD) ? Wl : Wr;
        int kk = kc & (DD - 1);
        // ---- A chunk: rows row0..row0+127, k = kk+lc .. +7 ----
        {
            float4 v0 = make_float4(0.f, 0.f, 0.f, 0.f), v1 = v0;
            if (row0 + lr < NN) {
                v0 = *(const float4*)&Asrc[(row0 + lr) * DD + kk + lc];
                v1 = *(const float4*)&Asrc[(row0 + lr) * DD + kk + lc + 4];
            }
            uint32_t* ph = &as_hi[lr * PAD + lc];
            uint32_t* pl = &as_lo[lr * PAD + lc];
            tf32_split(v0.x, ph[0], pl[0]); tf32_split(v0.y, ph[1], pl[1]);
            tf32_split(v0.z, ph[2], pl[2]); tf32_split(v0.w, ph[3], pl[3]);
            tf32_split(v1.x, ph[4], pl[4]); tf32_split(v1.y, ph[5], pl[5]);
            tf32_split(v1.z, ph[6], pl[6]); tf32_split(v1.w, ph[7], pl[7]);
        }
        // ---- B chunk: weight rows j = 0..127 (always valid) ----
        {
            float4 w0 = *(const float4*)&Bsrc[lr * DD + kk + lc];
            float4 w1 = *(const float4*)&Bsrc[lr * DD + kk + lc + 4];
            uint32_t* ph = &bs_hi[lr * PAD + lc];
            uint32_t* pl = &bs_lo[lr * PAD + lc];
            tf32_split(w0.x, ph[0], pl[0]); tf32_split(w0.y, ph[1], pl[1]);
            tf32_split(w0.z, ph[2], pl[2]); tf32_split(w0.w, ph[3], pl[3]);
            tf32_split(w1.x, ph[4], pl[4]); tf32_split(w1.y, ph[5], pl[5]);
            tf32_split(w1.z, ph[6], pl[6]); tf32_split(w1.w, ph[7], pl[7]);
        }
        __syncthreads();

#pragma unroll
        for (int ks = 0; ks < 16; ks += 8) {
            uint32_t ah[2][4], al[2][4];
#pragma unroll
            for (int mt = 0; mt < 2; mt++) {
                int r = (mbase + mt * 16 + grp) * PAD;
                int r8 = r + 8 * PAD;
                ah[mt][0] = as_hi[r + ks + thr];
                ah[mt][1] = as_hi[r8 + ks + thr];
                ah[mt][2] = as_hi[r + ks + thr + 4];
                ah[mt][3] = as_hi[r8 + ks + thr + 4];
                al[mt][0] = as_lo[r + ks + thr];
                al[mt][1] = as_lo[r8 + ks + thr];
                al[mt][2] = as_lo[r + ks + thr + 4];
                al[mt][3] = as_lo[r8 + ks + thr + 4];
            }
#pragma unroll
            for (int nt = 0; nt < 8; nt++) {
                int n = (nbase + nt * 8 + grp) * PAD;
                uint32_t bh[2], bl[2];
                bh[0] = bs_hi[n + ks + thr];
                bh[1] = bs_hi[n + ks + thr + 4];
                bl[0] = bs_lo[n + ks + thr];
                bl[1] = bs_lo[n + ks + thr + 4];
#pragma unroll
                for (int mt = 0; mt < 2; mt++) {
                    mma_tf32(d[mt][nt], ah[mt], bl);
                    mma_tf32(d[mt][nt], al[mt], bh);
                    mma_tf32(d[mt][nt], ah[mt], bh);
                }
            }
        }
        __syncthreads();
    }

    // epilogue: d fragment rows m = base + grp (+8); cols j = nbase + nt*8 + thr*2
#pragma unroll
    for (int mt = 0; mt < 2; mt++) {
        int m = row0 + mbase + mt * 16 + grp;
#pragma unroll
        for (int nt = 0; nt < 8; nt++) {
            int j = nbase + nt * 8 + thr * 2;
            if (m < NN)
                *(float2*)&g_h[m * DD + j] = make_float2(d[mt][nt][0], d[mt][nt][1]);
            if (m + 8 < NN)
                *(float2*)&g_h[(m + 8) * DD + j] = make_float2(d[mt][nt][2], d[mt][nt][3]);
        }
    }
}

// ==================== BN / residual / classifier ====================
__global__ void zero_stats_kernel() {
    int j = threadIdx.x;
    g_colsum[j] = 0.f;
    g_colsumsq[j] = 0.f;
}

__global__ void stats_kernel() {
    int j = threadIdx.x;   // 128 threads = 1 col each
    float s = 0.f, sq = 0.f;
    for (int r = blockIdx.x; r < NN; r += gridDim.x) {
        float v = g_h[r * DD + j];
        s += v;
        sq += v * v;
    }
    atomicAdd(&g_colsum[j], s);
    atomicAdd(&g_colsumsq[j], sq);
}

__global__ void bn_final_kernel(const float* __restrict__ g, const float* __restrict__ b) {
    int j = threadIdx.x;
    float mu = g_colsum[j] * (1.0f / NN);
    float var = g_colsumsq[j] * (1.0f / NN) - mu * mu;
    float sc = g[j] * rsqrtf(var + EPS);
    g_scale[j] = sc;
    g_shift[j] = b[j] - mu * sc;
}

__global__ void residual_kernel() {
    int i = blockIdx.x * blockDim.x + threadIdx.x;  // over N*D/4
    if (i >= NN * DD / 4) return;
    int j = (i & 31) * 4;
    float4 h = ((float4*)g_h)[i];
    float4 x = ((float4*)g_x)[i];
    float4 sc = *(float4*)&g_scale[j];
    float4 sh = *(float4*)&g_shift[j];
    x.x += fmaxf(h.x * sc.x + sh.x, 0.f);
    x.y += fmaxf(h.y * sc.y + sh.y, 0.f);
    x.z += fmaxf(h.z * sc.z + sh.z, 0.f);
    x.w += fmaxf(h.w * sc.w + sh.w, 0.f);
    ((float4*)g_x)[i] = x;
}

__global__ void final_gemm_kernel(const float* __restrict__ W,
                                  const float* __restrict__ b,
                                  float* __restrict__ out)
{
    __shared__ __align__(16) float xs[8][DD];
    int rb = blockIdx.x * 8;
    int tid = threadIdx.y * 48 + threadIdx.x;  // blockDim (48, 8)
    if (tid < 256) {
        int m = tid >> 5;
        int q = tid & 31;
        int row = rb + m;
        float4 v = make_float4(0.f, 0.f, 0.f, 0.f);
        if (row < NN) v = *(const float4*)&g_x[row * DD + q * 4];
        *(float4*)&xs[m][q * 4] = v;
    }
    __syncthreads();

    int c = threadIdx.x;
    int row = rb + threadIdx.y;
    if (row >= NN || c >= CC) return;
    float acc = 0.f;
#pragma unroll
    for (int k = 0; k < DD; k += 4) {
        float4 xv = *(float4*)&xs[threadIdx.y][k];
        float4 wv = *(const float4*)&W[c * DD + k];
        acc += xv.x * wv.x + xv.y * wv.y + xv.z * wv.z + xv.w * wv.w;
    }
    out[row * CC + c] = acc + __ldg(&b[c]);
}

// ==================== driver ====================
extern "C" void kernel_launch(void* const* d_in, const int* in_sizes, int n_in,
                              void* d_out, int out_size) {
    const float* x  = (const float*)d_in[0];
    const int*   ei = (const int*)d_in[1];
    float* out = (float*)d_out;

    copy_x_kernel<<<2048, 256>>>(x);
    hist_kernel<<<(EE + 255) / 256, 256>>>(ei);
    scan_kernel<<<1, 1024>>>();
    fill_kernel<<<(EE + 255) / 256, 256>>>(ei);

    for (int layer = 0; layer < 3; layer++) {
        const float* Wl = (const float*)d_in[2 + layer * 5 + 0];
        const float* Wr = (const float*)d_in[2 + layer * 5 + 2];
        const float* bg = (const float*)d_in[2 + layer * 5 + 3];
        const float* bb = (const float*)d_in[2 + layer * 5 + 4];

        gather_kernel<<<(NN * 32 + 255) / 256, 256>>>();
        gemm_mma_kernel<<<(NN + 127) / 128, 256>>>(Wl, Wr);
        zero_stats_kernel<<<1, 128>>>();
        stats_kernel<<<1024, 128>>>();
        bn_final_kernel<<<1, 128>>>(bg, bb);
        residual_kernel<<<(NN * DD / 4 + 255) / 256, 256>>>();
    }

    const float* linW = (const float*)d_in[17];
    const float* linb = (const float*)d_in[18];
    final_gemm_kernel<<<(NN + 7) / 8, dim3(48, 8)>>>(linW, linb, out);
}

// round 6
// speedup vs baseline: 1.6277x; 1.1330x over previous
#include <cuda_runtime.h>
#include <cuda_fp16.h>
#include <cstdint>

#define NN 100000
#define EE 1600000
#define DD 128
#define CC 47
#define EPS 1e-5f

// -------- scratch (device globals; no runtime allocation) --------
__device__ float g_x[NN * DD];
__device__ float g_msg[NN * DD];
__device__ float g_h[NN * DD];
__device__ int   g_deg[NN];
__device__ int   g_rowptr[NN];
__device__ int   g_cursor[NN];
__device__ int   g_srcs[EE];
__device__ float g_colsum[DD];
__device__ float g_colsumsq[DD];
__device__ float g_scale[DD];
__device__ float g_shift[DD];

// ==================== helpers ====================
__device__ __forceinline__ void split_pack(float f0, float f1, uint32_t& hi, uint32_t& lo) {
    __half h0 = __float2half_rn(f0);
    __half h1 = __float2half_rn(f1);
    __half l0 = __float2half_rn(f0 - __half2float(h0));
    __half l1 = __float2half_rn(f1 - __half2float(h1));
    __half2 hh = __halves2half2(h0, h1);
    __half2 ll = __halves2half2(l0, l1);
    hi = *(uint32_t*)&hh;
    lo = *(uint32_t*)&ll;
}
__device__ __forceinline__ void mma_f16(float* d, const uint32_t* a, const uint32_t* b) {
    asm volatile(
        "mma.sync.aligned.m16n8k16.row.col.f32.f16.f16.f32 "
        "{%0,%1,%2,%3}, {%4,%5,%6,%7}, {%8,%9}, {%0,%1,%2,%3};"
        : "+f"(d[0]), "+f"(d[1]), "+f"(d[2]), "+f"(d[3])
        : "r"(a[0]), "r"(a[1]), "r"(a[2]), "r"(a[3]), "r"(b[0]), "r"(b[1]));
}

// ==================== housekeeping ====================
__global__ void copy_x_kernel(const float* __restrict__ x) {
    int tid = blockIdx.x * blockDim.x + threadIdx.x;
    int stride = gridDim.x * blockDim.x;
    const float4* src = (const float4*)x;
    float4* dst = (float4*)g_x;
    for (int i = tid; i < NN * DD / 4; i += stride) dst[i] = src[i];
    for (int i = tid; i < NN; i += stride) g_deg[i] = 0;
}

__global__ void hist_kernel(const int* __restrict__ ei) {
    int e = blockIdx.x * blockDim.x + threadIdx.x;
    if (e >= EE) return;
    atomicAdd(&g_deg[ei[EE + e]], 1);
}

__global__ void scan_kernel() {
    __shared__ int wsums[32];
    int tid = threadIdx.x;            // 1024 threads
    int lane = tid & 31, wid = tid >> 5;
    int carry = 0;
    for (int base = 0; base < NN; base += 1024) {
        int i = base + tid;
        int v = (i < NN) ? g_deg[i] : 0;
        int x = v;
#pragma unroll
        for (int d = 1; d < 32; d <<= 1) {
            int y = __shfl_up_sync(0xffffffffu, x, d);
            if (lane >= d) x += y;
        }
        if (lane == 31) wsums[wid] = x;
        __syncthreads();
        if (wid == 0) {
            int s = wsums[lane];
#pragma unroll
            for (int d = 1; d < 32; d <<= 1) {
                int y = __shfl_up_sync(0xffffffffu, s, d);
                if (lane >= d) s += y;
            }
            wsums[lane] = s;
        }
        __syncthreads();
        int warpoff = (wid > 0) ? wsums[wid - 1] : 0;
        int excl = carry + warpoff + x - v;
        if (i < NN) { g_rowptr[i] = excl; g_cursor[i] = excl; }
        carry += wsums[31];
        __syncthreads();
    }
}

__global__ void fill_kernel(const int* __restrict__ ei) {
    int e = blockIdx.x * blockDim.x + threadIdx.x;
    if (e >= EE) return;
    int dst = ei[EE + e];
    int pos = atomicAdd(&g_cursor[dst], 1);
    g_srcs[pos] = ei[e];
}

// -------- aggregation: warp per node, mean of x[src]; also zeroes BN stats --------
__global__ void gather_kernel() {
    if (blockIdx.x == 0 && threadIdx.x < DD) {
        g_colsum[threadIdx.x] = 0.f;
        g_colsumsq[threadIdx.x] = 0.f;
    }
    int warp = (blockIdx.x * blockDim.x + threadIdx.x) >> 5;
    int lane = threadIdx.x & 31;
    if (warp >= NN) return;
    int start = g_rowptr[warp];
    int deg = g_deg[warp];
    float4 a0 = make_float4(0.f, 0.f, 0.f, 0.f);
    float4 a1 = a0, a2 = a0, a3 = a0;
    int e = 0;
    for (; e + 4 <= deg; e += 4) {
        int s0 = __ldg(&g_srcs[start + e]);
        int s1 = __ldg(&g_srcs[start + e + 1]);
        int s2 = __ldg(&g_srcs[start + e + 2]);
        int s3 = __ldg(&g_srcs[start + e + 3]);
        float4 v0 = *(const float4*)&g_x[s0 * DD + lane * 4];
        float4 v1 = *(const float4*)&g_x[s1 * DD + lane * 4];
        float4 v2 = *(const float4*)&g_x[s2 * DD + lane * 4];
        float4 v3 = *(const float4*)&g_x[s3 * DD + lane * 4];
        a0.x += v0.x; a0.y += v0.y; a0.z += v0.z; a0.w += v0.w;
        a1.x += v1.x; a1.y += v1.y; a1.z += v1.z; a1.w += v1.w;
        a2.x += v2.x; a2.y += v2.y; a2.z += v2.z; a2.w += v2.w;
        a3.x += v3.x; a3.y += v3.y; a3.z += v3.z; a3.w += v3.w;
    }
    for (; e < deg; e++) {
        int s0 = __ldg(&g_srcs[start + e]);
        float4 v0 = *(const float4*)&g_x[s0 * DD + lane * 4];
        a0.x += v0.x; a0.y += v0.y; a0.z += v0.z; a0.w += v0.w;
    }
    float rc = 1.0f / (float)(deg > 0 ? deg : 1);
    a0.x = (a0.x + a1.x + a2.x + a3.x) * rc;
    a0.y = (a0.y + a1.y + a2.y + a3.y) * rc;
    a0.z = (a0.z + a1.z + a2.z + a3.z) * rc;
    a0.w = (a0.w + a1.w + a2.w + a3.w) * rc;
    *(float4*)&g_msg[warp * DD + lane * 4] = a0;
}

// ==================== mma.sync fp16-split layer GEMM ====================
// h[m][j] = sum_k x[m][k]*Wl[j][k] + sum_k mean[m][k]*Wr[j][k]  (bias dropped: BN-invariant)
// fp32 emulated via fp16 hi/lo split: d += ah*bh + ah*bl + al*bh  (al*bl ~2^-22 dropped)
// CTA tile 128x128, 8 warps (4 M x 2 N), warp tile 32x64, K chunked by 32 floats.
// SMEM arrays hold half2-packed values: [row][k/2] with row stride PAD uint32.
#define PAD 20
__global__ void __launch_bounds__(256, 2) gemm_mma_kernel(
    const float* __restrict__ Wl, const float* __restrict__ Wr)
{
    __shared__ uint32_t as_hi[128 * PAD];
    __shared__ uint32_t as_lo[128 * PAD];
    __shared__ uint32_t bs_hi[128 * PAD];
    __shared__ uint32_t bs_lo[128 * PAD];

    int tid = threadIdx.x;
    int wid = tid >> 5, lane = tid & 31;
    int grp = lane >> 2, thr = lane & 3;
    int row0 = blockIdx.x * 128;
    int mbase = (wid & 3) * 32;
    int nbase = (wid >> 2) * 64;

    float d[2][8][4];
#pragma unroll
    for (int mt = 0; mt < 2; mt++)
#pragma unroll
        for (int nt = 0; nt < 8; nt++)
#pragma unroll
            for (int i = 0; i < 4; i++) d[mt][nt][i] = 0.f;

    int lr = tid >> 1;           // 0..127 (row)
    int lc = (tid & 1) * 16;     // float-k offset within 32-float chunk

    for (int kc = 0; kc < 2 * DD; kc += 32) {
        const float* Asrc = (kc < DD) ? g_x : g_msg;
        const float* Bsrc = (kc < DD) ? Wl : Wr;
        int kk = (kc & (DD - 1)) + lc;
        // ---- A chunk: 16 floats of row lr -> 8 hi + 8 lo packed half2 ----
        {
            float4 v0 = make_float4(0.f, 0.f, 0.f, 0.f), v1 = v0, v2 = v0, v3 = v0;
            if (row0 + lr < NN) {
                const float* p = &Asrc[(row0 + lr) * DD + kk];
                v0 = *(const float4*)(p);
                v1 = *(const float4*)(p + 4);
                v2 = *(const float4*)(p + 8);
                v3 = *(const float4*)(p + 12);
            }
            uint32_t h[8], l[8];
            split_pack(v0.x, v0.y, h[0], l[0]); split_pack(v0.z, v0.w, h[1], l[1]);
            split_pack(v1.x, v1.y, h[2], l[2]); split_pack(v1.z, v1.w, h[3], l[3]);
            split_pack(v2.x, v2.y, h[4], l[4]); split_pack(v2.z, v2.w, h[5], l[5]);
            split_pack(v3.x, v3.y, h[6], l[6]); split_pack(v3.z, v3.w, h[7], l[7]);
            uint32_t base = (uint32_t)(lr * PAD + lc / 2);
            *(uint4*)&as_hi[base]     = make_uint4(h[0], h[1], h[2], h[3]);
            *(uint4*)&as_hi[base + 4] = make_uint4(h[4], h[5], h[6], h[7]);
            *(uint4*)&as_lo[base]     = make_uint4(l[0], l[1], l[2], l[3]);
            *(uint4*)&as_lo[base + 4] = make_uint4(l[4], l[5], l[6], l[7]);
        }
        // ---- B chunk: weight row lr (always valid) ----
        {
            const float* p = &Bsrc[lr * DD + kk];
            float4 w0 = *(const float4*)(p);
            float4 w1 = *(const float4*)(p + 4);
            float4 w2 = *(const float4*)(p + 8);
            float4 w3 = *(const float4*)(p + 12);
            uint32_t h[8], l[8];
            split_pack(w0.x, w0.y, h[0], l[0]); split_pack(w0.z, w0.w, h[1], l[1]);
            split_pack(w1.x, w1.y, h[2], l[2]); split_pack(w1.z, w1.w, h[3], l[3]);
            split_pack(w2.x, w2.y, h[4], l[4]); split_pack(w2.z, w2.w, h[5], l[5]);
            split_pack(w3.x, w3.y, h[6], l[6]); split_pack(w3.z, w3.w, h[7], l[7]);
            uint32_t base = (uint32_t)(lr * PAD + lc / 2);
            *(uint4*)&bs_hi[base]     = make_uint4(h[0], h[1], h[2], h[3]);
            *(uint4*)&bs_hi[base + 4] = make_uint4(h[4], h[5], h[6], h[7]);
            *(uint4*)&bs_lo[base]     = make_uint4(l[0], l[1], l[2], l[3]);
            *(uint4*)&bs_lo[base + 4] = make_uint4(l[4], l[5], l[6], l[7]);
        }
        __syncthreads();

#pragma unroll
        for (int s = 0; s < 2; s++) {        // two k16 steps per chunk
            int ko = s * 8 + thr;            // uint32 column
            uint32_t ah[2][4], al[2][4];
#pragma unroll
            for (int mt = 0; mt < 2; mt++) {
                int r = (mbase + mt * 16 + grp) * PAD;
                int r8 = r + 8 * PAD;
                ah[mt][0] = as_hi[r + ko];
                ah[mt][1] = as_hi[r8 + ko];
                ah[mt][2] = as_hi[r + ko + 4];
                ah[mt][3] = as_hi[r8 + ko + 4];
                al[mt][0] = as_lo[r + ko];
                al[mt][1] = as_lo[r8 + ko];
                al[mt][2] = as_lo[r + ko + 4];
                al[mt][3] = as_lo[r8 + ko + 4];
            }
#pragma unroll
            for (int nt = 0; nt < 8; nt++) {
                int n = (nbase + nt * 8 + grp) * PAD;
                uint32_t bh[2], bl[2];
                bh[0] = bs_hi[n + ko];
                bh[1] = bs_hi[n + ko + 4];
                bl[0] = bs_lo[n + ko];
                bl[1] = bs_lo[n + ko + 4];
#pragma unroll
                for (int mt = 0; mt < 2; mt++) {
                    mma_f16(d[mt][nt], ah[mt], bl);
                    mma_f16(d[mt][nt], al[mt], bh);
                    mma_f16(d[mt][nt], ah[mt], bh);
                }
            }
        }
        __syncthreads();
    }

    // epilogue: d rows m = base + grp (+8); cols j = nbase + nt*8 + thr*2
#pragma unroll
    for (int mt = 0; mt < 2; mt++) {
        int m = row0 + mbase + mt * 16 + grp;
#pragma unroll
        for (int nt = 0; nt < 8; nt++) {
            int j = nbase + nt * 8 + thr * 2;
            if (m < NN)
                *(float2*)&g_h[m * DD + j] = make_float2(d[mt][nt][0], d[mt][nt][1]);
            if (m + 8 < NN)
                *(float2*)&g_h[(m + 8) * DD + j] = make_float2(d[mt][nt][2], d[mt][nt][3]);
        }
    }
}

// ==================== BN / residual / classifier ====================
__global__ void stats_kernel() {
    int j = threadIdx.x;   // 128 threads = 1 col each
    float s = 0.f, sq = 0.f;
    for (int r = blockIdx.x; r < NN; r += gridDim.x) {
        float v = g_h[r * DD + j];
        s += v;
        sq += v * v;
    }
    atomicAdd(&g_colsum[j], s);
    atomicAdd(&g_colsumsq[j], sq);
}

__global__ void bn_final_kernel(const float* __restrict__ g, const float* __restrict__ b) {
    int j = threadIdx.x;
    float mu = g_colsum[j] * (1.0f / NN);
    float var = g_colsumsq[j] * (1.0f / NN) - mu * mu;
    float sc = g[j] * rsqrtf(var + EPS);
    g_scale[j] = sc;
    g_shift[j] = b[j] - mu * sc;
}

__global__ void residual_kernel() {
    int i = blockIdx.x * blockDim.x + threadIdx.x;  // over N*D/4
    if (i >= NN * DD / 4) return;
    int j = (i & 31) * 4;
    float4 h = ((float4*)g_h)[i];
    float4 x = ((float4*)g_x)[i];
    float4 sc = *(float4*)&g_scale[j];
    float4 sh = *(float4*)&g_shift[j];
    x.x += fmaxf(h.x * sc.x + sh.x, 0.f);
    x.y += fmaxf(h.y * sc.y + sh.y, 0.f);
    x.z += fmaxf(h.z * sc.z + sh.z, 0.f);
    x.w += fmaxf(h.w * sc.w + sh.w, 0.f);
    ((float4*)g_x)[i] = x;
}

__global__ void final_gemm_kernel(const float* __restrict__ W,
                                  const float* __restrict__ b,
                                  float* __restrict__ out)
{
    __shared__ __align__(16) float xs[8][DD];
    int rb = blockIdx.x * 8;
    int tid = threadIdx.y * 48 + threadIdx.x;  // blockDim (48, 8)
    if (tid < 256) {
        int m = tid >> 5;
        int q = tid & 31;
        int row = rb + m;
        float4 v = make_float4(0.f, 0.f, 0.f, 0.f);
        if (row < NN) v = *(const float4*)&g_x[row * DD + q * 4];
        *(float4*)&xs[m][q * 4] = v;
    }
    __syncthreads();

    int c = threadIdx.x;
    int row = rb + threadIdx.y;
    if (row >= NN || c >= CC) return;
    float acc = 0.f;
#pragma unroll
    for (int k = 0; k < DD; k += 4) {
        float4 xv = *(float4*)&xs[threadIdx.y][k];
        float4 wv = *(const float4*)&W[c * DD + k];
        acc += xv.x * wv.x + xv.y * wv.y + xv.z * wv.z + xv.w * wv.w;
    }
    out[row * CC + c] = acc + __ldg(&b[c]);
}

// ==================== driver ====================
extern "C" void kernel_launch(void* const* d_in, const int* in_sizes, int n_in,
                              void* d_out, int out_size) {
    const float* x  = (const float*)d_in[0];
    const int*   ei = (const int*)d_in[1];
    float* out = (float*)d_out;

    copy_x_kernel<<<2048, 256>>>(x);
    hist_kernel<<<(EE + 255) / 256, 256>>>(ei);
    scan_kernel<<<1, 1024>>>();
    fill_kernel<<<(EE + 255) / 256, 256>>>(ei);

    for (int layer = 0; layer < 3; layer++) {
        const float* Wl = (const float*)d_in[2 + layer * 5 + 0];
        const float* Wr = (const float*)d_in[2 + layer * 5 + 2];
        const float* bg = (const float*)d_in[2 + layer * 5 + 3];
        const float* bb = (const float*)d_in[2 + layer * 5 + 4];

        gather_kernel<<<(NN * 32 + 255) / 256, 256>>>();
        gemm_mma_kernel<<<(NN + 127) / 128, 256>>>(Wl, Wr);
        stats_kernel<<<1024, 128>>>();
        bn_final_kernel<<<1, 128>>>(bg, bb);
        residual_kernel<<<(NN * DD / 4 + 255) / 256, 256>>>();
    }

    const float* linW = (const float*)d_in[17];
    const float* linb = (const float*)d_in[18];
    final_gemm_kernel<<<(NN + 7) / 8, dim3(48, 8)>>>(linW, linb, out);
}